// round 7
// baseline (speedup 1.0000x reference)
#include <cuda_runtime.h>
#include <math_constants.h>

// CropProposals: 3D ROI 2x2x2 adaptive max-pool.
// fm:      (4, 64, 24, 24, 24) f32   -> d_in[0]
// corners: (4, 64, 2, 3)       f32   -> d_in[1]
// out:     (4, 64, 64, 2, 2, 2) f32
//
// Vectorized-row scheme: one LDG.128 covers 5 full h-rows of a d-slice
// (lanes 0-29: row = L/6, z = 4*(L%6); 24 % 4 == 0 so each float4 is inside
// one row). Bins per axis are two EQUAL-length segments of (n+1)/2 (middle
// slice simply processed by both bins). 2 warps per (b,p,c) split by d-pair
// parity; block = 8 warps sharing one (b,p) -> uniform duration. kz binning
// via per-element z-masks + redux.sync on order-preserving keys.

#define NEGINF (-CUDART_INF_F)
#define KEY_NEGINF 0x007FFFFFu   // f2key(-inf)

__device__ __forceinline__ unsigned f2key(float f) {
    int i = __float_as_int(f);
    return (unsigned)(i ^ ((i >> 31) | 0x80000000));
}
__device__ __forceinline__ float key2f(unsigned u) {
    int i = (int)(u ^ ((~u >> 31) ? 0xFFFFFFFFu : 0x80000000u));
    return __int_as_float(i);
}

__device__ __forceinline__ void max4(float4& a, const float4& v) {
    a.x = fmaxf(a.x, v.x); a.y = fmaxf(a.y, v.y);
    a.z = fmaxf(a.z, v.z); a.w = fmaxf(a.w, v.w);
}

__global__ __launch_bounds__(256) void crop_proposals_kernel(
    const float* __restrict__ fm,
    const float* __restrict__ corners,
    float* __restrict__ out)
{
    __shared__ unsigned skey[8][8];

    const int wid   = threadIdx.x >> 5;   // 0..7
    const int lane  = threadIdx.x & 31;
    const int cpair = wid >> 1;           // channel within block
    const int half  = wid & 1;            // d-parity split

    const int bp = blockIdx.x >> 4;       // b*64 + p
    const int cg = blockIdx.x & 15;       // channel group
    const int b  = bp >> 6;
    const int c  = cg * 4 + cpair;

    // ---- bin computation (matches JAX _pool_masks exactly, fp32) ----
    const float* cor = corners + bp * 6;
    int blo[3], nn[3];
#pragma unroll
    for (int a = 0; a < 3; a++) {
        float ll = cor[a]     * 0.25f;
        float ur = cor[3 + a] * 0.25f;
        ll = fminf(fmaxf(ll, 0.0f), 21.0f);
        ur = (ur - ll >= 2.0f) ? ur : (ll + 2.0f);
        ur = fminf(fmaxf(ur, 2.0f), 23.0f);
        int lo = (int)floorf(ll);
        blo[a] = lo;
        nn[a]  = (int)floorf(ur) - lo;     // n in [2, 23]
    }
    // per-axis: two segments [lo, lo+m2) and [lo+n/2, lo+n/2+m2), m2=(n+1)/2
    const int d0  = blo[0], dml = blo[0] + (nn[0] >> 1), md  = (nn[0] + 1) >> 1;
    const int h0  = blo[1], hml = blo[1] + (nn[1] >> 1), mh2 = (nn[1] + 1) >> 1;
    const int zlo = blo[2], zml = blo[2] + (nn[2] >> 1), mz2 = (nn[2] + 1) >> 1;
    const int nch = (mh2 + 4) / 5;        // 5-row chunks per h-segment

    // ---- lane mapping: lanes 0..29 -> (row L/6, z 4*(L%6)); 30,31 dup 29 ----
    const int Lc = min(lane, 29);
    const int rl = Lc / 6;                 // row-in-chunk 0..4
    const int zq = 4 * (Lc % 6);           // z of element 0
    const int laneoff = rl * 24 + zq;

    const float* base = fm + ((size_t)(b * 64 + c)) * 13824;
    const int ddelta = (dml - d0) * 576;   // stream A -> stream C offset

    float4 accA[2], accC[2];               // [h-seg]; A=kx0, C=kx1
#pragma unroll
    for (int s = 0; s < 2; s++) {
        accA[s] = make_float4(NEGINF, NEGINF, NEGINF, NEGINF);
        accC[s] = make_float4(NEGINF, NEGINF, NEGINF, NEGINF);
    }

    // ---- main loop: this warp takes d-pair i = half, half+2, ... < md ----
    for (int i = half; i < md; i += 2) {
        const float* pA = base + (d0 + i) * 576;
#pragma unroll
        for (int s = 0; s < 2; s++) {
            const int s0 = s ? hml : h0;
            for (int k = 0; k < nch; k++) {
                const int start = min(s0 + 5 * k, 19);   // rows start..start+4 <= 23
                const bool pv = (unsigned)(start + rl - s0) < (unsigned)mh2;
                const float* q = pA + start * 24 + laneoff;
                const float4 vA = __ldg((const float4*)q);
                const float4 vC = __ldg((const float4*)(q + ddelta));
                if (pv) { max4(accA[s], vA); max4(accC[s], vC); }
            }
        }
    }

    // ---- epilogue: kz binning via per-element z masks + redux ----
    // acc order q: 0=kx0ky0(A,s0) 1=kx0ky1(A,s1) 2=kx1ky0(C,s0) 3=kx1ky1(C,s1)
#pragma unroll
    for (int q = 0; q < 4; q++) {
        const float4 v = (q < 2) ? accA[q & 1] : accC[q & 1];
#pragma unroll
        for (int kz = 0; kz < 2; kz++) {
            const int zb = kz ? zml : zlo;     // bin [zb, zb + mz2)
            float t0 = ((unsigned)(zq + 0 - zb) < (unsigned)mz2) ? v.x : NEGINF;
            float t1 = ((unsigned)(zq + 1 - zb) < (unsigned)mz2) ? v.y : NEGINF;
            float t2 = ((unsigned)(zq + 2 - zb) < (unsigned)mz2) ? v.z : NEGINF;
            float t3 = ((unsigned)(zq + 3 - zb) < (unsigned)mz2) ? v.w : NEGINF;
            float t = fmaxf(fmaxf(t0, t1), fmaxf(t2, t3));
            unsigned mk = __reduce_max_sync(0xFFFFFFFFu, f2key(t));
            if (lane == 0) skey[wid][q * 2 + kz] = mk;   // slot = kx*4+ky*2+kz
        }
    }
    __syncthreads();

    // ---- combine halves + write: warp 0, one lane per output value ----
    if (wid == 0) {
        const int ocp = lane >> 3;     // channel pair 0..3
        const int k   = lane & 7;      // output slot kx*4+ky*2+kz
        unsigned v = max(skey[ocp * 2 + 0][k], skey[ocp * 2 + 1][k]);
        const int oc = cg * 4 + ocp;
        out[(((size_t)bp * 64 + oc) << 3) + k] = key2f(v);
    }
}

extern "C" void kernel_launch(void* const* d_in, const int* in_sizes, int n_in,
                              void* d_out, int out_size)
{
    const float* fm      = (const float*)d_in[0];
    const float* corners = (const float*)d_in[1];
    float* out           = (float*)d_out;

    // 256 (b,p) x 16 channel-groups = 4096 blocks, 8 warps each
    crop_proposals_kernel<<<4096, 256>>>(fm, corners, out);
}

// round 8
// speedup vs baseline: 1.1786x; 1.1786x over previous
#include <cuda_runtime.h>
#include <math_constants.h>

// CropProposals: 3D ROI 2x2x2 adaptive max-pool — smem-resident volume version.
// fm:      (4, 64, 24, 24, 24) f32   -> d_in[0]
// corners: (4, 64, 2, 3)       f32   -> d_in[1]
// out:     (4, 64, 64, 2, 2, 2) f32
//
// One block per (b,c): 256 blocks, each stages its 24^3 volume (55 KB) into
// dynamic smem once, then processes all 64 proposals from smem (LDS, 29 cyc).
// Warp-pair q handles proposals q, q+4, ...; within a pair the two warps split
// the fused d-loop by parity (equal outer segments, shared middle slice to
// half 1). Lanes span z; per-warp z-binning via redux.sync on order-preserving
// keys; halves land in disjoint smem slots, combined in a final pass.

#define NEGINF (-CUDART_INF_F)
#define KEY_NEGINF 0x007FFFFFu   // f2key(-inf)

#define VOL_FLOATS 13824
#define SKEY_OFF   13824          // 64 proposals * 2 halves * 8 slots (u32)
#define COR_OFF    (13824 + 1024) // 64 proposals * 6 floats
#define SMEM_FLOATS (13824 + 1024 + 384)

__device__ __forceinline__ unsigned f2key(float f) {
    int i = __float_as_int(f);
    return (unsigned)(i ^ ((i >> 31) | 0x80000000));
}
__device__ __forceinline__ float key2f(unsigned u) {
    int i = (int)(u ^ ((~u >> 31) ? 0xFFFFFFFFu : 0x80000000u));
    return __int_as_float(i);
}

__global__ __launch_bounds__(256) void crop_proposals_kernel(
    const float* __restrict__ fm,
    const float* __restrict__ corners,
    float* __restrict__ out)
{
    extern __shared__ float smem[];
    float*    vol   = smem;
    unsigned* skey  = (unsigned*)(smem + SKEY_OFF);   // [p][half][8]
    float*    cor_s = smem + COR_OFF;                 // [p][6]

    const int tid  = threadIdx.x;
    const int wid  = tid >> 5;          // 0..7
    const int lane = tid & 31;
    const int q    = wid >> 1;          // warp pair 0..3
    const int half = wid & 1;           // d-parity split

    const int c = blockIdx.x & 63;
    const int b = blockIdx.x >> 6;

    // ---- stage: volume, corners, skey init ----
    {
        const float4* vsrc = (const float4*)(fm + ((size_t)(b * 64 + c)) * VOL_FLOATS);
        float4* vdst = (float4*)vol;
        for (int i = tid; i < VOL_FLOATS / 4; i += 256)
            vdst[i] = __ldg(vsrc + i);
        for (int i = tid; i < 384; i += 256)
            cor_s[i] = __ldg(corners + b * 384 + i);
        for (int i = tid; i < 1024; i += 256)
            skey[i] = KEY_NEGINF;
    }
    __syncthreads();

    // ---- compute: proposals p = q, q+4, ..., 60 for this warp pair ----
    for (int p = q; p < 64; p += 4) {
        const float* cor = cor_s + p * 6;
        int blo[3], bmh[3], bhi[3], m[3], odd[3];
#pragma unroll
        for (int a = 0; a < 3; a++) {
            float ll = cor[a]     * 0.25f;
            float ur = cor[3 + a] * 0.25f;
            ll = fminf(fmaxf(ll, 0.0f), 21.0f);
            ur = (ur - ll >= 2.0f) ? ur : (ll + 2.0f);
            ur = fminf(fmaxf(ur, 2.0f), 23.0f);
            int lo = (int)floorf(ll);
            int n  = (int)floorf(ur) - lo;
            blo[a] = lo;
            bmh[a] = lo + ((n + 1) >> 1);
            bhi[a] = lo + n;
            m[a]   = n >> 1;
            odd[a] = n & 1;
        }

        const float* base = vol + lane;   // lanes 24-31 read junk, masked later
        const int hA0 = blo[1] * 24;
        const int hC0 = bmh[1] * 24;
        const int hM  = (blo[1] + m[1]) * 24;
        const int mh  = m[1];

        float a00 = NEGINF, a01 = NEGINF, a10 = NEGINF, a11 = NEGINF;

        for (int i = half; i < m[0]; i += 2) {
            const float* pA = base + (blo[0] + i) * 576;
            const float* pC = base + (bmh[0] + i) * 576;
            const float* qA0 = pA + hA0;
            const float* qA1 = pA + hC0;
            const float* qC0 = pC + hA0;
            const float* qC1 = pC + hC0;
            int j = 0;
            for (; j + 1 < mh; j += 2) {
                float v0 = qA0[0],  v1 = qA1[0];
                float v2 = qC0[0],  v3 = qC1[0];
                float w0 = qA0[24], w1 = qA1[24];
                float w2 = qC0[24], w3 = qC1[24];
                a00 = fmaxf(a00, fmaxf(v0, w0));
                a01 = fmaxf(a01, fmaxf(v1, w1));
                a10 = fmaxf(a10, fmaxf(v2, w2));
                a11 = fmaxf(a11, fmaxf(v3, w3));
                qA0 += 48; qA1 += 48; qC0 += 48; qC1 += 48;
            }
            if (j < mh) {
                a00 = fmaxf(a00, qA0[0]);
                a01 = fmaxf(a01, qA1[0]);
                a10 = fmaxf(a10, qC0[0]);
                a11 = fmaxf(a11, qC1[0]);
            }
            if (odd[1]) {     // shared middle h row -> both ky bins
                float vA = pA[hM];
                float vC = pC[hM];
                a00 = fmaxf(a00, vA); a01 = fmaxf(a01, vA);
                a10 = fmaxf(a10, vC); a11 = fmaxf(a11, vC);
            }
        }

        if (odd[0] && half == 1) {   // middle d slice -> both kx bins
            const float* pM = base + (blo[0] + m[0]) * 576;
            const float* q0 = pM + hA0;
            const float* q1 = pM + hC0;
            float r0 = NEGINF, r1 = NEGINF;
            int j = 0;
            for (; j + 1 < mh; j += 2) {
                float v0 = q0[0],  v1 = q1[0];
                float w0 = q0[24], w1 = q1[24];
                r0 = fmaxf(r0, fmaxf(v0, w0));
                r1 = fmaxf(r1, fmaxf(v1, w1));
                q0 += 48; q1 += 48;
            }
            if (j < mh) {
                r0 = fmaxf(r0, q0[0]);
                r1 = fmaxf(r1, q1[0]);
            }
            if (odd[1]) {
                float vm = pM[hM];
                r0 = fmaxf(r0, vm);
                r1 = fmaxf(r1, vm);
            }
            a00 = fmaxf(a00, r0); a10 = fmaxf(a10, r0);
            a01 = fmaxf(a01, r1); a11 = fmaxf(a11, r1);
        }

        // ---- z-bin reductions via redux.sync on monotone keys ----
        const unsigned k00 = f2key(a00), k01 = f2key(a01);
        const unsigned k10 = f2key(a10), k11 = f2key(a11);
        unsigned* slot = skey + (p * 2 + half) * 8;
#pragma unroll
        for (int kz = 0; kz < 2; kz++) {
            const bool inz = kz ? (lane >= blo[2] + m[2] && lane < bhi[2])
                                : (lane >= blo[2]        && lane < bmh[2]);
            unsigned m00 = __reduce_max_sync(0xFFFFFFFFu, inz ? k00 : KEY_NEGINF);
            unsigned m01 = __reduce_max_sync(0xFFFFFFFFu, inz ? k01 : KEY_NEGINF);
            unsigned m10 = __reduce_max_sync(0xFFFFFFFFu, inz ? k10 : KEY_NEGINF);
            unsigned m11 = __reduce_max_sync(0xFFFFFFFFu, inz ? k11 : KEY_NEGINF);
            if (lane == 0) {
                slot[kz + 0] = m00;   // slot index = kx*4 + ky*2 + kz
                slot[kz + 2] = m01;
                slot[kz + 4] = m10;
                slot[kz + 6] = m11;
            }
        }
    }
    __syncthreads();

    // ---- combine halves + write out: 512 values, 2 per thread ----
    for (int idx = tid; idx < 512; idx += 256) {
        const int p = idx >> 3;
        const int k = idx & 7;
        unsigned v = max(skey[(p * 2 + 0) * 8 + k], skey[(p * 2 + 1) * 8 + k]);
        out[(((size_t)(b * 64 + p)) * 64 + c) * 8 + k] = key2f(v);
    }
}

extern "C" void kernel_launch(void* const* d_in, const int* in_sizes, int n_in,
                              void* d_out, int out_size)
{
    const float* fm      = (const float*)d_in[0];
    const float* corners = (const float*)d_in[1];
    float* out           = (float*)d_out;

    static int configured = 0;
    if (!configured) {
        cudaFuncSetAttribute(crop_proposals_kernel,
                             cudaFuncAttributeMaxDynamicSharedMemorySize,
                             SMEM_FLOATS * 4);
        configured = 1;
    }
    // 256 blocks = (b, c); 8 warps each; 61 KB dynamic smem
    crop_proposals_kernel<<<256, 256, SMEM_FLOATS * 4>>>(fm, corners, out);
}

// round 9
// speedup vs baseline: 1.2193x; 1.0345x over previous
#include <cuda_runtime.h>
#include <math_constants.h>

// CropProposals: 3D ROI 2x2x2 adaptive max-pool — smem-resident volume, v2.
// fm:      (4, 64, 24, 24, 24) f32   -> d_in[0]
// corners: (4, 64, 2, 3)       f32   -> d_in[1]
// out:     (4, 64, 64, 2, 2, 2) f32
//
// 4 blocks per (b,c) = 1024 blocks; each stages the 24^3 volume (55.3 KB)
// into dynamic smem (L2-served, fm is L2-resident) and processes 16 of the
// 64 proposals. smem/block = 56.3 KB -> 4 blocks/SM = 32 warps/SM resident.
// Warp-pair q takes proposals p = sub + 4*(q + 4*t); within a pair the two
// warps split the fused d-loop by parity. Lanes span z (contiguous, LDS
// conflict-free); z-binning via redux.sync on order-preserving keys.

#define NEGINF (-CUDART_INF_F)
#define KEY_NEGINF 0x007FFFFFu   // f2key(-inf)

#define VOL_FLOATS 13824
#define SKEY_OFF   13824               // 16 proposals * 2 halves * 8 slots
#define SMEM_FLOATS (13824 + 256)

__device__ __forceinline__ unsigned f2key(float f) {
    int i = __float_as_int(f);
    return (unsigned)(i ^ ((i >> 31) | 0x80000000));
}
__device__ __forceinline__ float key2f(unsigned u) {
    int i = (int)(u ^ ((~u >> 31) ? 0xFFFFFFFFu : 0x80000000u));
    return __int_as_float(i);
}

__global__ __launch_bounds__(256) void crop_proposals_kernel(
    const float* __restrict__ fm,
    const float* __restrict__ corners,
    float* __restrict__ out)
{
    extern __shared__ float smem[];
    float*    vol  = smem;
    unsigned* skey = (unsigned*)(smem + SKEY_OFF);   // [16][half][8]

    const int tid  = threadIdx.x;
    const int wid  = tid >> 5;          // 0..7
    const int lane = tid & 31;
    const int q    = wid >> 1;          // warp pair 0..3
    const int half = wid & 1;           // d-parity split

    const int sub = blockIdx.x & 3;     // proposal sub-set
    const int bc  = blockIdx.x >> 2;    // b*64 + c
    const int c   = bc & 63;
    const int b   = bc >> 6;

    // ---- stage volume (L2-resident source) ----
    {
        const float4* vsrc = (const float4*)(fm + (size_t)bc * VOL_FLOATS);
        float4* vdst = (float4*)vol;
#pragma unroll
        for (int k = 0; k < 13; k++)
            vdst[tid + k * 256] = __ldg(vsrc + tid + k * 256);
        if (tid < 3456 - 13 * 256)
            vdst[tid + 13 * 256] = __ldg(vsrc + tid + 13 * 256);
    }
    __syncthreads();

    // ---- compute: 4 proposals per warp pair ----
#pragma unroll 1
    for (int t = 0; t < 4; t++) {
        const int pj = q + 4 * t;               // 0..15 within block
        const int p  = sub + 4 * pj;            // global proposal id
        const float* cor = corners + (b * 64 + p) * 6;

        int blo[3], bmh[3], bhi[3], m[3], odd[3];
#pragma unroll
        for (int a = 0; a < 3; a++) {
            float ll = __ldg(cor + a)     * 0.25f;
            float ur = __ldg(cor + 3 + a) * 0.25f;
            ll = fminf(fmaxf(ll, 0.0f), 21.0f);
            ur = (ur - ll >= 2.0f) ? ur : (ll + 2.0f);
            ur = fminf(fmaxf(ur, 2.0f), 23.0f);
            int lo = (int)floorf(ll);
            int n  = (int)floorf(ur) - lo;
            blo[a] = lo;
            bmh[a] = lo + ((n + 1) >> 1);
            bhi[a] = lo + n;
            m[a]   = n >> 1;
            odd[a] = n & 1;
        }

        const float* base = vol + lane;   // lanes 24-31 read junk, masked later
        const int hA0 = blo[1] * 24;
        const int hC0 = bmh[1] * 24;
        const int hM  = (blo[1] + m[1]) * 24;
        const int mh  = m[1];

        float a00 = NEGINF, a01 = NEGINF, a10 = NEGINF, a11 = NEGINF;

        for (int i = half; i < m[0]; i += 2) {
            const float* pA = base + (blo[0] + i) * 576;
            const float* pC = base + (bmh[0] + i) * 576;
            const float* qA0 = pA + hA0;
            const float* qA1 = pA + hC0;
            const float* qC0 = pC + hA0;
            const float* qC1 = pC + hC0;
            int j = 0;
            for (; j + 1 < mh; j += 2) {
                float v0 = qA0[0],  v1 = qA1[0];
                float v2 = qC0[0],  v3 = qC1[0];
                float w0 = qA0[24], w1 = qA1[24];
                float w2 = qC0[24], w3 = qC1[24];
                a00 = fmaxf(a00, fmaxf(v0, w0));
                a01 = fmaxf(a01, fmaxf(v1, w1));
                a10 = fmaxf(a10, fmaxf(v2, w2));
                a11 = fmaxf(a11, fmaxf(v3, w3));
                qA0 += 48; qA1 += 48; qC0 += 48; qC1 += 48;
            }
            if (j < mh) {
                a00 = fmaxf(a00, qA0[0]);
                a01 = fmaxf(a01, qA1[0]);
                a10 = fmaxf(a10, qC0[0]);
                a11 = fmaxf(a11, qC1[0]);
            }
            if (odd[1]) {     // shared middle h row -> both ky bins
                float vA = pA[hM];
                float vC = pC[hM];
                a00 = fmaxf(a00, vA); a01 = fmaxf(a01, vA);
                a10 = fmaxf(a10, vC); a11 = fmaxf(a11, vC);
            }
        }

        if (odd[0] && half == 1) {   // middle d slice -> both kx bins
            const float* pM = base + (blo[0] + m[0]) * 576;
            const float* q0 = pM + hA0;
            const float* q1 = pM + hC0;
            float r0 = NEGINF, r1 = NEGINF;
            int j = 0;
            for (; j + 1 < mh; j += 2) {
                float v0 = q0[0],  v1 = q1[0];
                float w0 = q0[24], w1 = q1[24];
                r0 = fmaxf(r0, fmaxf(v0, w0));
                r1 = fmaxf(r1, fmaxf(v1, w1));
                q0 += 48; q1 += 48;
            }
            if (j < mh) {
                r0 = fmaxf(r0, q0[0]);
                r1 = fmaxf(r1, q1[0]);
            }
            if (odd[1]) {
                float vm = pM[hM];
                r0 = fmaxf(r0, vm);
                r1 = fmaxf(r1, vm);
            }
            a00 = fmaxf(a00, r0); a10 = fmaxf(a10, r0);
            a01 = fmaxf(a01, r1); a11 = fmaxf(a11, r1);
        }

        // ---- z-bin reductions via redux.sync on monotone keys ----
        const unsigned k00 = f2key(a00), k01 = f2key(a01);
        const unsigned k10 = f2key(a10), k11 = f2key(a11);
        unsigned* slot = skey + (pj * 2 + half) * 8;
#pragma unroll
        for (int kz = 0; kz < 2; kz++) {
            const bool inz = kz ? (lane >= blo[2] + m[2] && lane < bhi[2])
                                : (lane >= blo[2]        && lane < bmh[2]);
            unsigned m00 = __reduce_max_sync(0xFFFFFFFFu, inz ? k00 : KEY_NEGINF);
            unsigned m01 = __reduce_max_sync(0xFFFFFFFFu, inz ? k01 : KEY_NEGINF);
            unsigned m10 = __reduce_max_sync(0xFFFFFFFFu, inz ? k10 : KEY_NEGINF);
            unsigned m11 = __reduce_max_sync(0xFFFFFFFFu, inz ? k11 : KEY_NEGINF);
            if (lane == 0) {
                slot[kz + 0] = m00;   // slot index = kx*4 + ky*2 + kz
                slot[kz + 2] = m01;
                slot[kz + 4] = m10;
                slot[kz + 6] = m11;
            }
        }
    }
    __syncthreads();

    // ---- combine halves + write out: 128 values ----
    if (tid < 128) {
        const int pj = tid >> 3;
        const int k  = tid & 7;
        const int p  = sub + 4 * pj;
        unsigned v = max(skey[(pj * 2 + 0) * 8 + k], skey[(pj * 2 + 1) * 8 + k]);
        out[(((size_t)(b * 64 + p)) * 64 + c) * 8 + k] = key2f(v);
    }
}

extern "C" void kernel_launch(void* const* d_in, const int* in_sizes, int n_in,
                              void* d_out, int out_size)
{
    const float* fm      = (const float*)d_in[0];
    const float* corners = (const float*)d_in[1];
    float* out           = (float*)d_out;

    static int configured = 0;
    if (!configured) {
        cudaFuncSetAttribute(crop_proposals_kernel,
                             cudaFuncAttributeMaxDynamicSharedMemorySize,
                             SMEM_FLOATS * 4);
        configured = 1;
    }
    // 1024 blocks = (b,c) x 4 proposal subsets; 8 warps, 56.3 KB smem each
    crop_proposals_kernel<<<1024, 256, SMEM_FLOATS * 4>>>(fm, corners, out);
}